// round 2
// baseline (speedup 1.0000x reference)
#include <cuda_runtime.h>
#include <cuda_bf16.h>

// SIR scan: out[0]=i0; for t in [0,T-1): i'=i+i*c_t*s-k*i; r'=r+k*i; s'=1-r'-i';
// out[t+1]=i'+r'.  Nonlinear recurrence -> sequential, BUT in fp32 the output
// freezes (bitwise) once i is small enough; we detect that rigorously (using
// global bounds on c_t) and fill the constant tail in parallel.

#define NB1    256
#define NT1    256
#define CHUNK  4096
#define NT2    1024

__device__ float g_bmax[NB1];     // per-block max of c
__device__ float g_bmin[NB1];     // per-block min of c
__device__ int   g_tstar;         // first index of constant tail (== T if none)
__device__ float g_rconst;        // constant tail value

__device__ __forceinline__ float dot6(const float* __restrict__ x, int t,
                                      float b0, float b1, float b2,
                                      float b3, float b4, float b5) {
    // row starts at byte offset 24*t -> always 8B aligned: three float2 loads
    const float2* row = reinterpret_cast<const float2*>(x + 6 * t);
    float2 a0 = __ldg(row + 0);
    float2 a1 = __ldg(row + 1);
    float2 a2 = __ldg(row + 2);
    return a0.x * b0 + a0.y * b1 + a1.x * b2 +
           a1.y * b3 + a2.x * b4 + a2.y * b5;
}

// ---------------------------------------------------------------------------
// Kernel 1: global max/min of c[t] = x[t,0:6] @ b (no c written to memory).
// Needed so the freeze predicate can bound ALL future growth factors.
// ---------------------------------------------------------------------------
__global__ void sir_minmax_kernel(const float* __restrict__ x,
                                  const float* __restrict__ b, int T) {
    const float b0 = __ldg(b + 0), b1 = __ldg(b + 1), b2 = __ldg(b + 2);
    const float b3 = __ldg(b + 3), b4 = __ldg(b + 4), b5 = __ldg(b + 5);
    float mx = -3.4e38f, mn = 3.4e38f;
    const int stride = gridDim.x * blockDim.x;
    for (int t = blockIdx.x * blockDim.x + threadIdx.x; t < T; t += stride) {
        float c = dot6(x, t, b0, b1, b2, b3, b4, b5);
        mx = fmaxf(mx, c);
        mn = fminf(mn, c);
    }
    #pragma unroll
    for (int o = 16; o; o >>= 1) {
        mx = fmaxf(mx, __shfl_xor_sync(0xFFFFFFFFu, mx, o));
        mn = fminf(mn, __shfl_xor_sync(0xFFFFFFFFu, mn, o));
    }
    __shared__ float smx[NT1 / 32], smn[NT1 / 32];
    const int wid = threadIdx.x >> 5, lid = threadIdx.x & 31;
    if (lid == 0) { smx[wid] = mx; smn[wid] = mn; }
    __syncthreads();
    if (threadIdx.x == 0) {
        float M = smx[0], m = smn[0];
        #pragma unroll
        for (int w = 1; w < NT1 / 32; w++) {
            M = fmaxf(M, smx[w]);
            m = fminf(m, smn[w]);
        }
        g_bmax[blockIdx.x] = M;
        g_bmin[blockIdx.x] = m;
    }
}

// ---------------------------------------------------------------------------
// Kernel 2: single-block sequential scan. Staging threads compute c for a
// 4096-step chunk directly from x into shared memory (scan thread never eats
// global latency); thread 0 runs the recurrence in the reference's operation
// order, checking a rounding-rigorous freeze predicate each step:
//   - r + k*i  == r   (r frozen for all smaller-or-equal i; rounding monotone)
//   - i + r    == r   (out == r for all smaller-or-equal i)
//   - (1-k) + cmax*(1-r) < 1  (growth factor <= 1 for any future c_t and any
//                              s <= 1-r  -> i non-increasing)
//   - (1-k) + cmin*(1-r) > 0  (factor positive -> i stays in (0, i])
// Once all hold, out[tau] == r bitwise for every future tau.
// ---------------------------------------------------------------------------
__global__ void sir_scan_kernel(const float* __restrict__ x,
                                const float* __restrict__ b,
                                const float* __restrict__ kptr,
                                float* __restrict__ out, int T) {
    __shared__ float sc[CHUNK];
    __shared__ float s_cmax, s_cmin;
    __shared__ int   s_done;

    const float b0 = __ldg(b + 0), b1 = __ldg(b + 1), b2 = __ldg(b + 2);
    const float b3 = __ldg(b + 3), b4 = __ldg(b + 4), b5 = __ldg(b + 5);

    // reduce the NB1 per-block maxima/minima with warp 0
    if (threadIdx.x < 32) {
        float mx = -3.4e38f, mn = 3.4e38f;
        for (int j = threadIdx.x; j < NB1; j += 32) {
            mx = fmaxf(mx, g_bmax[j]);
            mn = fminf(mn, g_bmin[j]);
        }
        #pragma unroll
        for (int o = 16; o; o >>= 1) {
            mx = fmaxf(mx, __shfl_xor_sync(0xFFFFFFFFu, mx, o));
            mn = fminf(mn, __shfl_xor_sync(0xFFFFFFFFu, mn, o));
        }
        if (threadIdx.x == 0) { s_cmax = mx; s_cmin = mn; s_done = 0; }
    }
    __syncthreads();

    const float i0    = 5.6e-06f;
    const float kab   = fabsf(__ldg(kptr));
    const float alpha = 1.0f - kab;

    float i = i0, r = 0.0f, s = 1.0f - i0;
    int   frozen = 0, tstar = T;
    float rconst = 0.0f;

    if (threadIdx.x == 0) out[0] = i0;

    const int Ns = T - 1;   // number of scan steps (consumes c[0..Ns-1])
    for (int base = 0; base < Ns; base += CHUNK) {
        const int n = min(CHUNK, Ns - base);
        for (int j = threadIdx.x; j < n; j += blockDim.x)
            sc[j] = dot6(x, base + j, b0, b1, b2, b3, b4, b5);
        __syncthreads();

        if (threadIdx.x == 0 && !frozen) {
            const float cmax = s_cmax;
            const float cmin = s_cmin;
            for (int j = 0; j < n; j++) {
                const float c  = sc[j];
                const float i2 = i + i * c * s - kab * i;
                const float r2 = r + kab * i;
                const float s2 = 1.0f - r2 - i2;
                out[base + j + 1] = i2 + r2;
                i = i2; r = r2; s = s2;

                if (i2 > 0.0f &&
                    __fadd_rn(r2, __fmul_rn(kab, i2)) == r2 &&
                    __fadd_rn(i2, r2) == r2) {
                    const float q = __fadd_rn(1.0f, -r2);   // sup of future s
                    if (__fadd_rn(alpha, __fmul_rn(cmax, q)) < 1.0f &&
                        __fadd_rn(alpha, __fmul_rn(cmin, q)) > 0.0f) {
                        frozen = 1;
                        tstar  = base + j + 2;  // out[base+j+1] already == r2
                        rconst = r2;
                        s_done = 1;
                        break;
                    }
                }
            }
        }
        __syncthreads();
        if (s_done) break;
    }

    if (threadIdx.x == 0) {
        g_tstar  = frozen ? tstar : T;
        g_rconst = rconst;
    }
}

// ---------------------------------------------------------------------------
// Kernel 3: parallel fill of the constant tail out[tstar .. T).
// ---------------------------------------------------------------------------
__global__ void sir_fill_kernel(float* __restrict__ out, int T) {
    const int   t0 = g_tstar;
    const float v  = g_rconst;
    const int stride = gridDim.x * blockDim.x;
    for (int t = t0 + blockIdx.x * blockDim.x + threadIdx.x; t < T; t += stride)
        out[t] = v;
}

// ---------------------------------------------------------------------------
extern "C" void kernel_launch(void* const* d_in, const int* in_sizes, int n_in,
                              void* d_out, int out_size) {
    const float* x = (const float*)d_in[0];   // [T, 6]
    const float* b = (const float*)d_in[1];   // [6, 1]
    const float* k = (const float*)d_in[2];   // [1, 1]
    float* out = (float*)d_out;               // [1, T]

    int T = in_sizes[0] / 6;
    if (T > out_size) T = out_size;
    if (T <= 0) return;

    sir_minmax_kernel<<<NB1, NT1>>>(x, b, T);
    sir_scan_kernel<<<1, NT2>>>(x, b, k, out, T);
    sir_fill_kernel<<<512, 256>>>(out, T);
}

// round 3
// speedup vs baseline: 1.3113x; 1.3113x over previous
#include <cuda_runtime.h>
#include <cuda_bf16.h>

// SIR scan: out[0]=i0; for t in [0,T-1): i'=i+i*c_t*s-k*i; r'=r+k*i; s'=1-r'-i';
// out[t+1]=i'+r'.  Nonlinear recurrence -> sequential, BUT in fp32 the output
// freezes (bitwise) once i is small enough; detected rigorously via global
// bounds on c_t, then the constant tail is filled in parallel.

#define G1     512          // minmax grid
#define NT1    256
#define CHUNK  1024
#define NT2    512

__device__ float g_bmax[G1];
__device__ float g_bmin[G1];
__device__ int   g_tstar;     // first index of constant tail (== T if none)
__device__ float g_rconst;    // constant tail value

// ---------------------------------------------------------------------------
// Kernel 1: global max/min of c[t] = x[t,0:6] @ b.  Row-pair float4 loads:
// 2 rows = 12 floats = 3 float4 (48B, 16B-aligned since 48*p % 16 == 0).
// ---------------------------------------------------------------------------
__global__ void sir_minmax_kernel(const float* __restrict__ x,
                                  const float* __restrict__ bp, int T) {
    const float b0 = __ldg(bp + 0), b1 = __ldg(bp + 1), b2 = __ldg(bp + 2);
    const float b3 = __ldg(bp + 3), b4 = __ldg(bp + 4), b5 = __ldg(bp + 5);
    float mx = -3.4e38f, mn = 3.4e38f;

    const float4* xv = reinterpret_cast<const float4*>(x);
    const int npairs = T >> 1;
    const int stride = gridDim.x * blockDim.x;
    for (int p = blockIdx.x * blockDim.x + threadIdx.x; p < npairs; p += stride) {
        float4 u = __ldg(xv + 3 * p + 0);
        float4 v = __ldg(xv + 3 * p + 1);
        float4 w = __ldg(xv + 3 * p + 2);
        float c0 = u.x * b0 + u.y * b1 + u.z * b2 + u.w * b3 + v.x * b4 + v.y * b5;
        float c1 = v.z * b0 + v.w * b1 + w.x * b2 + w.y * b3 + w.z * b4 + w.w * b5;
        mx = fmaxf(mx, fmaxf(c0, c1));
        mn = fminf(mn, fminf(c0, c1));
    }
    // odd-T tail row (handled by one thread; T=262144 -> no-op)
    if ((T & 1) && blockIdx.x == 0 && threadIdx.x == 0) {
        const float* row = x + 6 * (T - 1);
        float c = row[0] * b0 + row[1] * b1 + row[2] * b2 +
                  row[3] * b3 + row[4] * b4 + row[5] * b5;
        mx = fmaxf(mx, c);  mn = fminf(mn, c);
    }

    #pragma unroll
    for (int o = 16; o; o >>= 1) {
        mx = fmaxf(mx, __shfl_xor_sync(0xFFFFFFFFu, mx, o));
        mn = fminf(mn, __shfl_xor_sync(0xFFFFFFFFu, mn, o));
    }
    __shared__ float smx[NT1 / 32], smn[NT1 / 32];
    const int wid = threadIdx.x >> 5, lid = threadIdx.x & 31;
    if (lid == 0) { smx[wid] = mx; smn[wid] = mn; }
    __syncthreads();
    if (threadIdx.x == 0) {
        float M = smx[0], m = smn[0];
        #pragma unroll
        for (int w = 1; w < NT1 / 32; w++) { M = fmaxf(M, smx[w]); m = fminf(m, smn[w]); }
        g_bmax[blockIdx.x] = M;
        g_bmin[blockIdx.x] = m;
    }
}

// ---------------------------------------------------------------------------
// Kernel 2: single-block sequential scan with smem output buffer.
// Freeze predicate (all rounding-monotone in i):
//   i + r == r        (output frozen at r; implies r + k*i == r is also near —
//                      checked explicitly)
//   (1-k) + cmax*(1-r) < 1  -> growth factor <= 1 for ALL future c_t  (i non-inc)
//   (1-k) + cmin*(1-r) > 0  -> factor positive                        (i stays >0)
// Or i == 0 exactly (absorbing).  Then out[tau] == r bitwise forever.
// ---------------------------------------------------------------------------
__global__ void sir_scan_kernel(const float* __restrict__ x,
                                const float* __restrict__ bp,
                                const float* __restrict__ kptr,
                                float* __restrict__ out, int T) {
    __shared__ float sc[CHUNK];     // staged c values
    __shared__ float sout[CHUNK];   // staged outputs
    __shared__ float s_cmax, s_cmin;
    __shared__ int   s_stop;        // -1 = not frozen; else local freeze index

    const float b0 = __ldg(bp + 0), b1 = __ldg(bp + 1), b2 = __ldg(bp + 2);
    const float b3 = __ldg(bp + 3), b4 = __ldg(bp + 4), b5 = __ldg(bp + 5);

    if (threadIdx.x < 32) {
        float mx = -3.4e38f, mn = 3.4e38f;
        for (int j = threadIdx.x; j < G1; j += 32) {
            mx = fmaxf(mx, g_bmax[j]);
            mn = fminf(mn, g_bmin[j]);
        }
        #pragma unroll
        for (int o = 16; o; o >>= 1) {
            mx = fmaxf(mx, __shfl_xor_sync(0xFFFFFFFFu, mx, o));
            mn = fminf(mn, __shfl_xor_sync(0xFFFFFFFFu, mn, o));
        }
        if (threadIdx.x == 0) { s_cmax = mx; s_cmin = mn; }
    }

    const float i0    = 5.6e-06f;
    const float kab   = fabsf(__ldg(kptr));
    const float alpha = 1.0f - kab;

    float i = i0, r = 0.0f, s = 1.0f - i0;
    int   frozen = 0;
    int   tstar  = T;
    float rconst = 0.0f;

    if (threadIdx.x == 0) out[0] = i0;

    const int Ns = T - 1;
    for (int base = 0; base < Ns; base += CHUNK) {
        const int n = min(CHUNK, Ns - base);
        // stage c[base .. base+n) into smem
        for (int j = threadIdx.x; j < n; j += blockDim.x) {
            const float2* row = reinterpret_cast<const float2*>(x + 6 * (base + j));
            float2 a0 = __ldg(row + 0);
            float2 a1 = __ldg(row + 1);
            float2 a2 = __ldg(row + 2);
            sc[j] = a0.x * b0 + a0.y * b1 + a1.x * b2 +
                    a1.y * b3 + a2.x * b4 + a2.y * b5;
        }
        if (threadIdx.x == 0) s_stop = -1;
        __syncthreads();

        if (threadIdx.x == 0) {
            const float cmax = s_cmax, cmin = s_cmin;
            float c = sc[0];
            for (int j = 0; j < n; j++) {
                const float cn = (j + 1 < n) ? sc[j + 1] : 0.0f;  // prefetch
                const float ics = i * c;
                const float ia  = i * alpha;
                const float r2  = __fmaf_rn(kab, i, r);
                const float i2  = __fmaf_rn(ics, s, ia);    // i + i*c*s - k*i
                const float s2  = (1.0f - r2) - i2;
                const float o2  = __fadd_rn(i2, r2);
                sout[j] = o2;
                i = i2; r = r2; s = s2; c = cn;

                // cheap gate: o2 rounds back to r2 (latest-firing condition)
                if (o2 == r2) {
                    if (i2 == 0.0f) {                 // absorbing exactly
                        s_stop = j; frozen = 1;
                        tstar = base + j + 2; rconst = r2;
                        break;
                    }
                    if (i2 > 0.0f &&
                        __fadd_rn(r2, __fmul_rn(kab, i2)) == r2) {
                        const float q = __fadd_rn(1.0f, -r2);   // sup future s
                        if (__fadd_rn(alpha, __fmul_rn(cmax, q)) < 1.0f &&
                            __fadd_rn(alpha, __fmul_rn(cmin, q)) > 0.0f) {
                            s_stop = j; frozen = 1;
                            tstar = base + j + 2; rconst = r2;
                            break;
                        }
                    }
                }
            }
        }
        __syncthreads();

        const int stop = s_stop;
        const int m = (stop >= 0) ? (stop + 1) : n;   // outputs to flush
        for (int j = threadIdx.x; j < m; j += blockDim.x)
            out[base + 1 + j] = sout[j];
        if (stop >= 0) break;
        __syncthreads();
    }

    if (threadIdx.x == 0) {
        g_tstar  = frozen ? tstar : T;
        g_rconst = rconst;
    }
}

// ---------------------------------------------------------------------------
// Kernel 3: vectorized parallel fill of out[tstar .. T) with rconst.
// ---------------------------------------------------------------------------
__global__ void sir_fill_kernel(float* __restrict__ out, int T) {
    const int   t0 = g_tstar;
    const float v  = g_rconst;
    if (t0 >= T) return;

    const int gid    = blockIdx.x * blockDim.x + threadIdx.x;
    const int stride = gridDim.x * blockDim.x;

    const int a0 = (t0 + 3) & ~3;             // first 16B-aligned index
    if (gid < a0 - t0 && t0 + gid < T) out[t0 + gid] = v;

    float4* o4 = reinterpret_cast<float4*>(out + a0);
    const int n4 = (T > a0) ? ((T - a0) >> 2) : 0;
    const float4 v4 = make_float4(v, v, v, v);
    for (int j = gid; j < n4; j += stride) o4[j] = v4;

    const int tail = a0 + (n4 << 2);
    if (gid < T - tail) out[tail + gid] = v;
}

// ---------------------------------------------------------------------------
extern "C" void kernel_launch(void* const* d_in, const int* in_sizes, int n_in,
                              void* d_out, int out_size) {
    const float* x = (const float*)d_in[0];   // [T, 6]
    const float* b = (const float*)d_in[1];   // [6, 1]
    const float* k = (const float*)d_in[2];   // [1, 1]
    float* out = (float*)d_out;               // [1, T]

    int T = in_sizes[0] / 6;
    if (T > out_size) T = out_size;
    if (T <= 0) return;

    sir_minmax_kernel<<<G1, NT1>>>(x, b, T);
    sir_scan_kernel<<<1, NT2>>>(x, b, k, out, T);
    sir_fill_kernel<<<256, 256>>>(out, T);
}

// round 6
// speedup vs baseline: 1.5296x; 1.1664x over previous
#include <cuda_runtime.h>
#include <cuda_bf16.h>

// SIR scan with fp32 bitwise-freeze detection.
//   out[0]=i0; step: i'=i+i*c_t*s-k*i; r'=r+k*i; s'=1-r'-i'; out[t+1]=i'+r'.
// Two launches:
//   K1 main : block 0 runs the serial recurrence until the cheap freeze
//             candidate fires (o==r bitwise and r+k*i==r), checkpoints;
//             blocks 1..NB2 concurrently compute global max/min of
//             c[t]=x[t,:]@b (BW-optimized).  All 129 blocks are wave-1
//             resident -> true overlap.
//   K2 tail : verify the rigorous growth-factor bound (guarantees the
//             candidate freeze holds for ALL future c_t); parallel-fill the
//             constant tail; else (adversarial input only) serial fallback.

#define NB2    128          // minmax blocks (partials count)
#define NTS    512          // threads per block in K1
#define CHUNK  1024
#define NB3    128          // tail grid
#define NT3    256

__device__ float g_bmax[NB2];
__device__ float g_bmin[NB2];
__device__ int   g_cand;      // 0 = scanned everything; 1 = candidate; 2 = i hit 0
__device__ int   g_tstar;     // first tail index (out[g_tstar..T) constant)
__device__ float g_rconst;
__device__ float g_ci, g_cr, g_cs;   // checkpoint state (time g_tstar-1)

__device__ __forceinline__ float dot6(const float* __restrict__ x, int t,
                                      float b0, float b1, float b2,
                                      float b3, float b4, float b5) {
    const float2* row = reinterpret_cast<const float2*>(x + 6 * t);
    float2 a0 = __ldg(row + 0);
    float2 a1 = __ldg(row + 1);
    float2 a2 = __ldg(row + 2);
    return a0.x * b0 + a0.y * b1 + a1.x * b2 +
           a1.y * b3 + a2.x * b4 + a2.y * b5;
}

// ---------------------------------------------------------------------------
// K1: fused scan (block 0) + minmax (blocks 1..NB2).
// ---------------------------------------------------------------------------
__global__ void __launch_bounds__(NTS, 1)
sir_main_kernel(const float* __restrict__ x,
                const float* __restrict__ bp,
                const float* __restrict__ kptr,
                float* __restrict__ out, int T) {
    const float b0 = __ldg(bp + 0), b1 = __ldg(bp + 1), b2 = __ldg(bp + 2);
    const float b3 = __ldg(bp + 3), b4 = __ldg(bp + 4), b5 = __ldg(bp + 5);

    if (blockIdx.x == 0) {
        // ----------------- serial scan with smem staging -----------------
        __shared__ float sc[CHUNK];
        __shared__ float sout[CHUNK];
        __shared__ int   s_stop;

        const float i0    = 5.6e-06f;
        const float kab   = fabsf(__ldg(kptr));
        const float alpha = 1.0f - kab;

        float i = i0, r = 0.0f, s = 1.0f - i0;
        int   cand = 0, tstar = T;
        float rconst = 0.0f;
        float ci = i0, cr = 0.0f, cs = s;

        if (threadIdx.x == 0) out[0] = i0;

        const int Ns = T - 1;
        for (int base = 0; base < Ns; base += CHUNK) {
            const int n = min(CHUNK, Ns - base);
            for (int j = threadIdx.x; j < n; j += NTS)
                sc[j] = dot6(x, base + j, b0, b1, b2, b3, b4, b5);
            if (threadIdx.x == 0) s_stop = -1;
            __syncthreads();

            if (threadIdx.x == 0 && !cand) {
                float c = sc[0];
                for (int j = 0; j < n; j++) {
                    const float cn  = (j + 1 < n) ? sc[j + 1] : 0.0f;  // prefetch
                    const float ics = i * c;
                    const float ia  = i * alpha;
                    const float r2  = __fmaf_rn(kab, i, r);
                    const float i2  = __fmaf_rn(ics, s, ia);  // i + i*c*s - k*i
                    const float s2  = (1.0f - r2) - i2;
                    const float o2  = __fadd_rn(i2, r2);
                    sout[j] = o2;
                    i = i2; r = r2; s = s2; c = cn;

                    if (o2 == r2) {
                        if (i2 == 0.0f) {          // absorbing: frozen forever
                            cand = 2;
                        } else if (i2 > 0.0f &&
                                   __fadd_rn(r2, __fmul_rn(kab, i2)) == r2) {
                            cand = 1;              // frozen iff growth bound holds
                        }
                        if (cand) {
                            s_stop = j;
                            tstar  = base + j + 2;
                            rconst = r2;
                            ci = i2; cr = r2; cs = s2;
                            break;
                        }
                    }
                }
            }
            __syncthreads();

            const int stop = s_stop;
            const int m = (stop >= 0) ? (stop + 1) : n;
            for (int j = threadIdx.x; j < m; j += NTS)
                out[base + 1 + j] = sout[j];
            if (stop >= 0) break;
            __syncthreads();
        }

        if (threadIdx.x == 0) {
            g_cand   = cand;
            g_tstar  = cand ? tstar : T;
            g_rconst = rconst;
            g_ci = ci; g_cr = cr; g_cs = cs;
        }
    } else {
        // ----------------- parallel max/min of c -----------------
        float mx = -3.4e38f, mn = 3.4e38f;

        const float4* xv = reinterpret_cast<const float4*>(x);
        const int npairs  = T >> 1;
        const int nthread = NB2 * NTS;
        const int tid     = (blockIdx.x - 1) * NTS + threadIdx.x;
        const int nbatch  = npairs >> 2;            // batches of 4 row-pairs

        for (int bidx = tid; bidx < nbatch; bidx += nthread) {
            const int p = bidx * 4;
            float4 v[12];
            #pragma unroll
            for (int q = 0; q < 12; q++) v[q] = __ldg(xv + 3 * p + q);
            #pragma unroll
            for (int q = 0; q < 4; q++) {
                float4 u  = v[3 * q + 0];
                float4 vv = v[3 * q + 1];
                float4 w  = v[3 * q + 2];
                float c0 = u.x * b0 + u.y * b1 + u.z * b2 + u.w * b3 + vv.x * b4 + vv.y * b5;
                float c1 = vv.z * b0 + vv.w * b1 + w.x * b2 + w.y * b3 + w.z * b4 + w.w * b5;
                mx = fmaxf(mx, fmaxf(c0, c1));
                mn = fminf(mn, fminf(c0, c1));
            }
        }
        // remainder rows [nbatch*8, T)
        for (int t = nbatch * 8 + tid; t < T; t += nthread) {
            float c = dot6(x, t, b0, b1, b2, b3, b4, b5);
            mx = fmaxf(mx, c);
            mn = fminf(mn, c);
        }

        #pragma unroll
        for (int o = 16; o; o >>= 1) {
            mx = fmaxf(mx, __shfl_xor_sync(0xFFFFFFFFu, mx, o));
            mn = fminf(mn, __shfl_xor_sync(0xFFFFFFFFu, mn, o));
        }
        __shared__ float smx[NTS / 32], smn[NTS / 32];
        const int wid = threadIdx.x >> 5, lid = threadIdx.x & 31;
        if (lid == 0) { smx[wid] = mx; smn[wid] = mn; }
        __syncthreads();
        if (threadIdx.x == 0) {
            float M = smx[0], m = smn[0];
            #pragma unroll
            for (int w = 1; w < NTS / 32; w++) { M = fmaxf(M, smx[w]); m = fminf(m, smn[w]); }
            g_bmax[blockIdx.x - 1] = M;
            g_bmin[blockIdx.x - 1] = m;
        }
    }
}

// ---------------------------------------------------------------------------
// K2: verify + fill (or serial fallback). Every block redoes the tiny final
// reduction (128 partials, L2-hot), checks the rigorous freeze bound:
//   (1-k) + cmax*(1-r) < 1-eps  -> i non-increasing for all future c_t, s<=1-r
//   (1-k) + cmin*(1-r) > +eps   -> i stays positive
// (eps guards dominate the <=2^-23 fp slack of evaluating the bound).
// Monotone rounding then keeps r+k*i==r and i+r==r for all smaller i, so
// out[tau] == r bitwise for every tau >= tstar.
// ---------------------------------------------------------------------------
__global__ void sir_tail_kernel(const float* __restrict__ x,
                                const float* __restrict__ bp,
                                const float* __restrict__ kptr,
                                float* __restrict__ out, int T) {
    const int cand = g_cand;
    if (cand == 0) return;                       // scan covered everything

    __shared__ float s_cmax, s_cmin;
    if (threadIdx.x < 32) {
        float mx = -3.4e38f, mn = 3.4e38f;
        for (int j = threadIdx.x; j < NB2; j += 32) {
            mx = fmaxf(mx, g_bmax[j]);
            mn = fminf(mn, g_bmin[j]);
        }
        #pragma unroll
        for (int o = 16; o; o >>= 1) {
            mx = fmaxf(mx, __shfl_xor_sync(0xFFFFFFFFu, mx, o));
            mn = fminf(mn, __shfl_xor_sync(0xFFFFFFFFu, mn, o));
        }
        if (threadIdx.x == 0) { s_cmax = mx; s_cmin = mn; }
    }
    __syncthreads();

    const int   t0  = g_tstar;
    const float rc  = g_rconst;
    const float kab   = fabsf(__ldg(kptr));
    const float alpha = 1.0f - kab;

    bool ok;
    if (cand == 2) {
        ok = true;                               // i == 0 exactly: absorbing
    } else {
        const float q = __fadd_rn(1.0f, -rc);    // sup of future s
        ok = (g_ci > 0.0f) &&
             (__fadd_rn(alpha, __fmul_rn(s_cmax, q)) < 0.9999999f) &&
             (__fadd_rn(alpha, __fmul_rn(s_cmin, q)) > 1e-6f);
    }

    if (ok) {
        // vectorized parallel fill of out[t0 .. T)
        const int gid    = blockIdx.x * blockDim.x + threadIdx.x;
        const int stride = gridDim.x * blockDim.x;
        const int a0 = (t0 + 3) & ~3;
        if (gid < a0 - t0 && t0 + gid < T) out[t0 + gid] = rc;
        float4* o4 = reinterpret_cast<float4*>(out + a0);
        const int n4 = (T > a0) ? ((T - a0) >> 2) : 0;
        const float4 v4 = make_float4(rc, rc, rc, rc);
        for (int j = gid; j < n4; j += stride) o4[j] = v4;
        const int tail = a0 + (n4 << 2);
        if (gid < T - tail) out[tail + gid] = rc;
    } else if (blockIdx.x == 0 && threadIdx.x == 0) {
        // correct-but-slow fallback: continue serially from the checkpoint
        const float b0 = __ldg(bp + 0), b1 = __ldg(bp + 1), b2 = __ldg(bp + 2);
        const float b3 = __ldg(bp + 3), b4 = __ldg(bp + 4), b5 = __ldg(bp + 5);
        float i = g_ci, r = g_cr, s = g_cs;
        for (int t = t0 - 1; t < T - 1; t++) {
            const float c  = dot6(x, t, b0, b1, b2, b3, b4, b5);
            const float r2 = __fmaf_rn(kab, i, r);
            const float i2 = __fmaf_rn(i * c, s, i * alpha);
            const float s2 = (1.0f - r2) - i2;
            out[t + 1] = __fadd_rn(i2, r2);
            i = i2; r = r2; s = s2;
        }
    }
}

// ---------------------------------------------------------------------------
extern "C" void kernel_launch(void* const* d_in, const int* in_sizes, int n_in,
                              void* d_out, int out_size) {
    const float* x = (const float*)d_in[0];   // [T, 6]
    const float* b = (const float*)d_in[1];   // [6, 1]
    const float* k = (const float*)d_in[2];   // [1, 1]
    float* out = (float*)d_out;               // [1, T]

    int T = in_sizes[0] / 6;
    if (T > out_size) T = out_size;
    if (T <= 0) return;

    sir_main_kernel<<<NB2 + 1, NTS>>>(x, b, k, out, T);
    sir_tail_kernel<<<NB3, NT3>>>(x, b, k, out, T);
}